// round 3
// baseline (speedup 1.0000x reference)
#include <cuda_runtime.h>
#include <math.h>

// ---------------- problem dims ----------------
#define BB   64
#define TT   64
#define DD   8
#define FF   1024
#define HH   1024
#define CC   22
#define INN  4096
#define NROW (BB*TT)      // 4096
#define G4   (4*HH)       // 4096 (also 4*FF)

// ---------------- scratch (static device allocations are allowed) ----------------
__device__ float g_feats[NROW*FF];
__device__ float g_h[NROW*HH];
__device__ float g_c[NROW*HH];
__device__ float g_gates[(size_t)NROW*G4];
__device__ float g_Wcomb[(size_t)G4*HH];
__device__ float g_bdec0[G4];
__device__ float g_bcomb[G4];
__device__ float g_benc[G4];

// ---------------- f32x2 helpers (Blackwell packed fp32) ----------------
typedef unsigned long long ULL;

__device__ __forceinline__ ULL pk2(float lo, float hi) {
    ULL r;
    asm("mov.b64 %0, {%1, %2};" : "=l"(r) : "f"(lo), "f"(hi));
    return r;
}
__device__ __forceinline__ void fma2(ULL& d, ULL a, ULL b) {
    asm("fma.rn.f32x2 %0, %1, %2, %0;" : "+l"(d) : "l"(a), "l"(b));
}

// ---------------- SGEMM: C[M,N] = act( A@B^T (+ alpha2*A2@B2^T) + bias (+ Cadd) ) ----------------
// BT=true : B is [N,K] row-major ("NT", used for all W^T products)
// BT=false: B is [K,N] row-major ("NN", used for Wih@Wdc)
// EPI: 0 = none, 1 = relu
#define BM 128
#define BN 128
#define BK 16
#define LDS 132   // padded smem row stride (floats); 132*4=528B, 16B-aligned rows

template<bool BT, int EPI>
__global__ __launch_bounds__(256, 2)
void sgemm_kernel(const float* __restrict__ A,  int lda,
                  const float* __restrict__ B,  int ldb,
                  const float* __restrict__ A2, int lda2,
                  const float* __restrict__ B2, int ldb2,
                  int K1, int K2, float alpha2,
                  const float* __restrict__ bias,
                  const float* __restrict__ Cadd, int ldadd,
                  float* __restrict__ C, int ldc)
{
    __shared__ __align__(16) float As[2][BK][LDS];
    __shared__ __align__(16) float Bs[2][BK][LDS];

    const int tid  = threadIdx.x;
    const int warp = tid >> 5;
    const int lane = tid & 31;
    const int wm = warp & 1;        // warp grid 2 (M) x 4 (N)
    const int wn = warp >> 1;
    const int lm = lane >> 2;       // lane grid 8 (M) x 4 (N)
    const int ln = lane & 3;

    const int bm = blockIdx.y * BM;
    const int bn = blockIdx.x * BN;

    const int aoff = wm * 64 + lm * 4;   // within-block row offset (plus +32 for 2nd quad)
    const int boff = wn * 32 + ln * 4;   // within-block col offset (plus +16 for 2nd quad)

    // global->smem loader indices
    const int arow0 = tid >> 2;          // 0..63 (rows; +64 for second half)
    const int ac4   = (tid & 3) * 4;     // k-subcolumn 0,4,8,12
    const int bkr0  = tid >> 5;          // NN: k row 0..7 (+8 for second half)
    const int bc4   = (tid & 31) * 4;    // NN: n column offset

    const int nk1 = K1 / BK;
    const int nk2 = K2 / BK;
    const int nkt = nk1 + nk2;

    ULL acc[8][4];
#pragma unroll
    for (int i = 0; i < 8; i++)
#pragma unroll
        for (int c = 0; c < 4; c++) acc[i][c] = 0ull;

    float4 ra0, ra1, rb0, rb1;

    auto ldg_tile = [&](int kt) {
        const float* Ap; int ldap; const float* Bp; int ldbp; int koff; float al;
        if (kt < nk1) { Ap = A;  ldap = lda;  Bp = B;  ldbp = ldb;  koff = kt * BK;          al = 1.0f;   }
        else          { Ap = A2; ldap = lda2; Bp = B2; ldbp = ldb2; koff = (kt - nk1) * BK;  al = alpha2; }
        ra0 = *(const float4*)(Ap + (size_t)(bm + arow0)      * ldap + koff + ac4);
        ra1 = *(const float4*)(Ap + (size_t)(bm + arow0 + 64) * ldap + koff + ac4);
        if (al != 1.0f) {
            ra0.x *= al; ra0.y *= al; ra0.z *= al; ra0.w *= al;
            ra1.x *= al; ra1.y *= al; ra1.z *= al; ra1.w *= al;
        }
        if (BT) {
            rb0 = *(const float4*)(Bp + (size_t)(bn + arow0)      * ldbp + koff + ac4);
            rb1 = *(const float4*)(Bp + (size_t)(bn + arow0 + 64) * ldbp + koff + ac4);
        } else {
            rb0 = *(const float4*)(Bp + (size_t)(koff + bkr0)     * ldbp + bn + bc4);
            rb1 = *(const float4*)(Bp + (size_t)(koff + bkr0 + 8) * ldbp + bn + bc4);
        }
    };

    auto sts_tile = [&](int s) {
        As[s][ac4 + 0][arow0]      = ra0.x;
        As[s][ac4 + 1][arow0]      = ra0.y;
        As[s][ac4 + 2][arow0]      = ra0.z;
        As[s][ac4 + 3][arow0]      = ra0.w;
        As[s][ac4 + 0][arow0 + 64] = ra1.x;
        As[s][ac4 + 1][arow0 + 64] = ra1.y;
        As[s][ac4 + 2][arow0 + 64] = ra1.z;
        As[s][ac4 + 3][arow0 + 64] = ra1.w;
        if (BT) {
            Bs[s][ac4 + 0][arow0]      = rb0.x;
            Bs[s][ac4 + 1][arow0]      = rb0.y;
            Bs[s][ac4 + 2][arow0]      = rb0.z;
            Bs[s][ac4 + 3][arow0]      = rb0.w;
            Bs[s][ac4 + 0][arow0 + 64] = rb1.x;
            Bs[s][ac4 + 1][arow0 + 64] = rb1.y;
            Bs[s][ac4 + 2][arow0 + 64] = rb1.z;
            Bs[s][ac4 + 3][arow0 + 64] = rb1.w;
        } else {
            *(float4*)&Bs[s][bkr0][bc4]     = rb0;
            *(float4*)&Bs[s][bkr0 + 8][bc4] = rb1;
        }
    };

    auto compute = [&](int s) {
#pragma unroll
        for (int k = 0; k < BK; k++) {
            float4 a0 = *(const float4*)&As[s][k][aoff];
            float4 a1 = *(const float4*)&As[s][k][aoff + 32];
            ulonglong2 b0 = *(const ulonglong2*)&Bs[s][k][boff];
            ulonglong2 b1 = *(const ulonglong2*)&Bs[s][k][boff + 16];
            float av[8] = {a0.x, a0.y, a0.z, a0.w, a1.x, a1.y, a1.z, a1.w};
#pragma unroll
            for (int i = 0; i < 8; i++) {
                ULL ad = pk2(av[i], av[i]);
                fma2(acc[i][0], ad, b0.x);
                fma2(acc[i][1], ad, b0.y);
                fma2(acc[i][2], ad, b1.x);
                fma2(acc[i][3], ad, b1.y);
            }
        }
    };

    ldg_tile(0);
    sts_tile(0);
    __syncthreads();

    int s = 0;
    for (int kt = 0; kt < nkt; kt++) {
        const bool pf = (kt + 1) < nkt;
        if (pf) ldg_tile(kt + 1);
        compute(s);
        if (pf) sts_tile(s ^ 1);
        __syncthreads();
        s ^= 1;
    }

    // epilogue
#pragma unroll
    for (int i = 0; i < 8; i++) {
        const int r = bm + aoff + (i < 4 ? i : 28 + i);   // second quad is +32
        float* crow = C + (size_t)r * ldc;
#pragma unroll
        for (int ch = 0; ch < 2; ch++) {
            const int cb = bn + boff + ch * 16;
            float2 p0 = *(float2*)&acc[i][ch * 2 + 0];
            float2 p1 = *(float2*)&acc[i][ch * 2 + 1];
            float4 v = make_float4(p0.x, p0.y, p1.x, p1.y);
            if (bias) {
                const float4 bv = *(const float4*)(bias + cb);
                v.x += bv.x; v.y += bv.y; v.z += bv.z; v.w += bv.w;
            }
            if (Cadd) {
                const float4 av2 = *(const float4*)(Cadd + (size_t)r * ldadd + cb);
                v.x += av2.x; v.y += av2.y; v.z += av2.z; v.w += av2.w;
            }
            if (EPI == 1) {
                v.x = fmaxf(v.x, 0.f); v.y = fmaxf(v.y, 0.f);
                v.z = fmaxf(v.z, 0.f); v.w = fmaxf(v.w, 0.f);
            }
            *(float4*)&crow[cb] = v;
        }
    }
}

// ---------------- LSTM pointwise ----------------
__device__ __forceinline__ float sigm(float x) { return 1.0f / (1.0f + expf(-x)); }

__global__ void lstm_kernel(const float* __restrict__ gates,
                            const float* __restrict__ cprev,   // null => zeros
                            float* __restrict__ h, float* __restrict__ c)
{
    const int idx = blockIdx.x * blockDim.x + threadIdx.x;     // over NROW*HH/4
    const int n  = idx >> 8;                                   // HH/4 = 256
    const int j4 = idx & 255;
    const float4* gp = (const float4*)(gates + (size_t)n * G4);
    const float4 gi = gp[j4];
    const float4 gf = gp[256 + j4];
    const float4 gg = gp[512 + j4];
    const float4 go = gp[768 + j4];
    float4 cp = make_float4(0.f, 0.f, 0.f, 0.f);
    if (cprev) cp = ((const float4*)cprev)[idx];
    float4 cn, hn;
    cn.x = sigm(gf.x) * cp.x + sigm(gi.x) * tanhf(gg.x);  hn.x = sigm(go.x) * tanhf(cn.x);
    cn.y = sigm(gf.y) * cp.y + sigm(gi.y) * tanhf(gg.y);  hn.y = sigm(go.y) * tanhf(cn.y);
    cn.z = sigm(gf.z) * cp.z + sigm(gi.z) * tanhf(gg.z);  hn.z = sigm(go.z) * tanhf(cn.z);
    cn.w = sigm(gf.w) * cp.w + sigm(gi.w) * tanhf(gg.w);  hn.w = sigm(go.w) * tanhf(cn.w);
    ((float4*)c)[idx] = cn;
    ((float4*)h)[idx] = hn;
}

// ---------------- bias prep: bdec0 = bih+bhh; bcomb = bdec0 + Wih@bdc; benc = ebih+ebhh ----------------
__global__ void prep_kernel(const float* __restrict__ dWih, const float* __restrict__ bdc,
                            const float* __restrict__ dbih, const float* __restrict__ dbhh,
                            const float* __restrict__ ebih, const float* __restrict__ ebhh,
                            float* __restrict__ bdec0, float* __restrict__ bcomb,
                            float* __restrict__ benc)
{
    const int g = blockIdx.x;       // 0..G4-1
    const int t = threadIdx.x;      // 128 threads
    float p = 0.f;
    for (int k = t; k < FF; k += 128) p += dWih[(size_t)g * FF + k] * bdc[k];
    p += __shfl_down_sync(0xffffffffu, p, 16);
    p += __shfl_down_sync(0xffffffffu, p, 8);
    p += __shfl_down_sync(0xffffffffu, p, 4);
    p += __shfl_down_sync(0xffffffffu, p, 2);
    p += __shfl_down_sync(0xffffffffu, p, 1);
    __shared__ float sred[4];
    if ((t & 31) == 0) sred[t >> 5] = p;
    __syncthreads();
    if (t == 0) {
        const float srow = sred[0] + sred[1] + sred[2] + sred[3];
        const float b0 = dbih[g] + dbhh[g];
        bdec0[g] = b0;
        bcomb[g] = b0 + srow;
        benc[g]  = ebih[g] + ebhh[g];
    }
}

// ---------------- skinny head: enc_scores[N,22] = h @ Wec^T + bec ----------------
__global__ void encscore_kernel(const float* __restrict__ h, const float* __restrict__ Wec,
                                const float* __restrict__ bec, float* __restrict__ out)
{
    const int warp = threadIdx.x >> 5;
    const int lane = threadIdx.x & 31;
    const int r = blockIdx.x * 8 + warp;   // grid = NROW/8
    float acc[CC];
#pragma unroll
    for (int n = 0; n < CC; n++) acc[n] = 0.f;
    const float* hr = h + (size_t)r * FF;
    for (int u = 0; u < FF / 32; u++) {
        const float hv = hr[u * 32 + lane];
#pragma unroll
        for (int n = 0; n < CC; n++) acc[n] += hv * Wec[n * FF + u * 32 + lane];
    }
#pragma unroll
    for (int n = 0; n < CC; n++) {
        float v = acc[n];
        v += __shfl_xor_sync(0xffffffffu, v, 16);
        v += __shfl_xor_sync(0xffffffffu, v, 8);
        v += __shfl_xor_sync(0xffffffffu, v, 4);
        v += __shfl_xor_sync(0xffffffffu, v, 2);
        v += __shfl_xor_sync(0xffffffffu, v, 1);
        if (lane == 0) out[(size_t)r * CC + n] = v + bec[n];
    }
}

// ---------------- launch ----------------
extern "C" void kernel_launch(void* const* d_in, const int* in_sizes, int n_in,
                              void* d_out, int out_size)
{
    const float* x    = (const float*)d_in[0];
    const float* Wf   = (const float*)d_in[1];
    const float* bf   = (const float*)d_in[2];
    const float* dWih = (const float*)d_in[3];
    const float* dWhh = (const float*)d_in[4];
    const float* dbih = (const float*)d_in[5];
    const float* dbhh = (const float*)d_in[6];
    const float* Wdc  = (const float*)d_in[7];
    const float* bdc  = (const float*)d_in[8];
    const float* eWih = (const float*)d_in[9];
    const float* eWhh = (const float*)d_in[10];
    const float* ebih = (const float*)d_in[11];
    const float* ebhh = (const float*)d_in[12];
    const float* Wec  = (const float*)d_in[13];
    const float* bec  = (const float*)d_in[14];

    float* enc_out = (float*)d_out;                              // [NROW, 22]
    float* dec_out = (float*)d_out + (size_t)NROW * CC;          // [NROW, D, F]

    float *feats, *hbuf, *cbuf, *gates, *Wcomb, *bdec0, *bcomb, *benc;
    cudaGetSymbolAddress((void**)&feats, g_feats);
    cudaGetSymbolAddress((void**)&hbuf,  g_h);
    cudaGetSymbolAddress((void**)&cbuf,  g_c);
    cudaGetSymbolAddress((void**)&gates, g_gates);
    cudaGetSymbolAddress((void**)&Wcomb, g_Wcomb);
    cudaGetSymbolAddress((void**)&bdec0, g_bdec0);
    cudaGetSymbolAddress((void**)&bcomb, g_bcomb);
    cudaGetSymbolAddress((void**)&benc,  g_benc);

    const dim3 gridBig(G4 / BN, NROW / BM);    // 32 x 32  (gates GEMMs)
    const dim3 gridOut(FF / BN, NROW / BM);    // 8  x 32  (out/feats/Wcomb GEMMs)
    const int  lstmGrid = NROW * HH / 4 / 256; // 4096

    // 1) feats = relu(x @ Wf^T + bf)        [NROW, FF], K=INN
    sgemm_kernel<true, 1><<<gridOut, 256>>>(x, INN, Wf, INN,
                                            nullptr, 0, nullptr, 0, INN, 0, 1.f,
                                            bf, nullptr, 0, feats, FF);

    // 2) Wcomb = dWih @ Wdc + dWhh          [G4, HH], K=FF   (NN)
    sgemm_kernel<false, 0><<<gridOut, 256>>>(dWih, FF, Wdc, HH,
                                             nullptr, 0, nullptr, 0, FF, 0, 1.f,
                                             nullptr, dWhh, HH, Wcomb, HH);

    // 3) bias prep
    prep_kernel<<<G4, 128>>>(dWih, bdc, dbih, dbhh, ebih, ebhh, bdec0, bcomb, benc);

    // 4) decoder step 0 (h0 = c0 = 0 -> gates = feats @ dWih^T + bih + bhh)
    sgemm_kernel<true, 0><<<gridBig, 256>>>(feats, FF, dWih, FF,
                                            nullptr, 0, nullptr, 0, FF, 0, 1.f,
                                            bdec0, nullptr, 0, gates, G4);
    lstm_kernel<<<lstmGrid, 256>>>(gates, nullptr, hbuf, cbuf);
    sgemm_kernel<true, 0><<<gridOut, 256>>>(hbuf, HH, Wdc, HH,
                                            nullptr, 0, nullptr, 0, HH, 0, 1.f,
                                            bdc, nullptr, 0, dec_out + 0 * FF, DD * FF);

    // 5) decoder steps 1..7: gates = h @ Wcomb^T + bcomb
    for (int t = 1; t < DD; t++) {
        sgemm_kernel<true, 0><<<gridBig, 256>>>(hbuf, HH, Wcomb, HH,
                                                nullptr, 0, nullptr, 0, HH, 0, 1.f,
                                                bcomb, nullptr, 0, gates, G4);
        lstm_kernel<<<lstmGrid, 256>>>(gates, cbuf, hbuf, cbuf);
        sgemm_kernel<true, 0><<<gridOut, 256>>>(hbuf, HH, Wdc, HH,
                                                nullptr, 0, nullptr, 0, HH, 0, 1.f,
                                                bdc, nullptr, 0, dec_out + t * FF, DD * FF);
    }

    // 6) encoder gates = feats @ eWih^T + (last_out/D) @ eWhh^T + ebih + ebhh
    sgemm_kernel<true, 0><<<gridBig, 256>>>(feats, FF, eWih, FF,
                                            dec_out + (DD - 1) * FF, DD * FF, eWhh, FF,
                                            FF, FF, 1.0f / (float)DD,
                                            benc, nullptr, 0, gates, G4);
    // encoder cell with c0 = 0
    lstm_kernel<<<lstmGrid, 256>>>(gates, nullptr, hbuf, cbuf);

    // 7) enc_scores = enc_h @ Wec^T + bec
    encscore_kernel<<<NROW / 8, 256>>>(hbuf, Wec, bec, enc_out);
}